// round 8
// baseline (speedup 1.0000x reference)
#include <cuda_runtime.h>
#include <cuda_fp16.h>
#include <cstdint>

// B=2, T=2048, C=1024, H=16, D=64, causal MHA, fp32 in/out.
#define BB 2
#define TT 2048
#define CC 1024
#define HH 16
#define DD 64
#define MM (BB*TT)

typedef __half h16;

// ---------------- scratch (allocation-free) ----------------
__device__ h16 g_xh[MM*CC], g_xl[MM*CC];
__device__ h16 g_ah[MM*CC], g_al[MM*CC];
__device__ h16 g_wh[4*CC*CC], g_wl[4*CC*CC];
__device__ h16 g_qh[BB*HH*TT*DD], g_ql[BB*HH*TT*DD];
__device__ h16 g_kh[BB*HH*TT*DD], g_kl[BB*HH*TT*DD];
__device__ h16 g_vh[BB*HH*TT*DD], g_vl[BB*HH*TT*DD];

// ---------------- helpers (sm_80-baseline PTX only) ----------------
__device__ __forceinline__ uint32_t smem_u32(const void* p) {
    return (uint32_t)__cvta_generic_to_shared(p);
}

#define CP16(dst, src) \
    asm volatile("cp.async.cg.shared.global [%0], [%1], 16;" :: "r"(dst), "l"(src) : "memory")
#define CP_COMMIT() asm volatile("cp.async.commit_group;" ::: "memory")
#define CP_WAIT(n)  asm volatile("cp.async.wait_group %0;" :: "n"(n) : "memory")

__device__ __forceinline__ void ldm4(uint32_t* r, uint32_t a) {
    asm volatile("ldmatrix.sync.aligned.m8n8.x4.shared.b16 {%0,%1,%2,%3}, [%4];"
                 : "=r"(r[0]), "=r"(r[1]), "=r"(r[2]), "=r"(r[3]) : "r"(a));
}
__device__ __forceinline__ void ldm4t(uint32_t* r, uint32_t a) {
    asm volatile("ldmatrix.sync.aligned.m8n8.x4.trans.shared.b16 {%0,%1,%2,%3}, [%4];"
                 : "=r"(r[0]), "=r"(r[1]), "=r"(r[2]), "=r"(r[3]) : "r"(a));
}
// f16 inputs, f32 accumulate (main products)
__device__ __forceinline__ void mma_f32(float* d, const uint32_t* a, const uint32_t* b) {
    asm volatile("mma.sync.aligned.m16n8k16.row.col.f32.f16.f16.f32 "
                 "{%0,%1,%2,%3}, {%4,%5,%6,%7}, {%8,%9}, {%0,%1,%2,%3};"
                 : "+f"(d[0]), "+f"(d[1]), "+f"(d[2]), "+f"(d[3])
                 : "r"(a[0]), "r"(a[1]), "r"(a[2]), "r"(a[3]), "r"(b[0]), "r"(b[1]));
}
// f16 inputs, f16 accumulate (correction products)
__device__ __forceinline__ void mma_f16(uint32_t* d, const uint32_t* a, const uint32_t* b) {
    asm volatile("mma.sync.aligned.m16n8k16.row.col.f16.f16.f16.f16 "
                 "{%0,%1}, {%2,%3,%4,%5}, {%6,%7}, {%0,%1};"
                 : "+r"(d[0]), "+r"(d[1])
                 : "r"(a[0]), "r"(a[1]), "r"(a[2]), "r"(a[3]), "r"(b[0]), "r"(b[1]));
}

__device__ __forceinline__ float2 h2f(uint32_t u) {
    __half2 h = *reinterpret_cast<__half2*>(&u);
    return __half22float2(h);
}
__device__ __forceinline__ uint32_t pk2h(float a, float b) {
    __half2 t = __floats2half2_rn(a, b);
    return *reinterpret_cast<uint32_t*>(&t);
}
__device__ __forceinline__ void split_st(h16* hi, h16* lo, size_t off, float a, float b) {
    __half h0 = __float2half_rn(a), h1 = __float2half_rn(b);
    *(__half2*)(hi + off) = __halves2half2(h0, h1);
    *(__half2*)(lo + off) = __floats2half2_rn(a - __half2float(h0), b - __half2float(h1));
}

// ---------------------------------------------------------------------------
__global__ void split_kernel(const float* __restrict__ x,
                             h16* __restrict__ hi, h16* __restrict__ lo) {
    int i = blockIdx.x * blockDim.x + threadIdx.x;
    float4 v = ((const float4*)x)[i];
    split_st(hi, lo, 4*(size_t)i,     v.x, v.y);
    split_st(hi, lo, 4*(size_t)i + 2, v.z, v.w);
}

// ---------------------------------------------------------------------------
__global__ void tsplit_kernel(const float* __restrict__ W0, const float* __restrict__ W1,
                              const float* __restrict__ W2, const float* __restrict__ W3,
                              h16* __restrict__ hi, h16* __restrict__ lo) {
    __shared__ float t[32][33];
    int tx = threadIdx.x, ty = threadIdx.y;          // (32, 8)
    int n0 = blockIdx.x * 32, k0 = blockIdx.y * 32;
    int z = blockIdx.z;
    const float* W = (z == 0) ? W0 : (z == 1) ? W1 : (z == 2) ? W2 : W3;
    h16* hz = hi + (size_t)z * CC * CC;
    h16* lz = lo + (size_t)z * CC * CC;
#pragma unroll
    for (int i = 0; i < 4; i++)
        t[ty + 8*i][tx] = W[(size_t)(k0 + ty + 8*i) * CC + n0 + tx];
    __syncthreads();
#pragma unroll
    for (int i = 0; i < 4; i++) {
        float v = t[tx][ty + 8*i];
        __half h = __float2half_rn(v);
        size_t o = (size_t)(n0 + ty + 8*i) * CC + k0 + tx;
        hz[o] = h;
        lz[o] = __float2half_rn(v - __half2float(h));
    }
}

// ---------------------------------------------------------------------------
// fp16x3 GEMM, corrections in f16-accumulate MMAs.
// Block 128x128, warp 64x32, K-chunk 64, 2-stage cp.async (128KB).
// Per tile: main Ah*Bh (f32 acc) + [Ah*Bl + Al*Bh] (f16 acc), folded at epilogue.
// MODE 0: split-fp16 output remapped to [B,H,T,D], scaled. MODE 1: fp32 [M,N].
// ---------------------------------------------------------------------------
#define GSTG 65536
#define NKT  16

template<int MODE>
__global__ __launch_bounds__(256) void gemm_f16x3(
    const h16* __restrict__ Ah, const h16* __restrict__ Al,
    const h16* __restrict__ Bh, const h16* __restrict__ Bl,
    const float* __restrict__ bias,
    float* __restrict__ outF, h16* __restrict__ outH, h16* __restrict__ outL,
    float scale)
{
    extern __shared__ char smraw[];
    const uint32_t sbase = smem_u32(smraw);

    int tid = threadIdx.x, lane = tid & 31, wid = tid >> 5;
    int wm = wid & 1, wn = wid >> 1;
    int m0 = blockIdx.y << 7, n0 = blockIdx.x << 7;

    float    acc[4][4][4] = {};
    uint32_t cac[4][4][2] = {};      // f16x2 correction accumulators

    auto load_stage = [&](int kt, int s) {
        uint32_t sb = sbase + (uint32_t)s * GSTG;
#pragma unroll
        for (int i = 0; i < 4; i++) {
            int id = tid + i*256;
            int r = id >> 3, c = id & 7;
            uint32_t phys = (uint32_t)(r*128 + ((c ^ (r & 7)) << 4));
            size_t ga = (size_t)(m0 + r)*CC + kt*64 + c*8;
            size_t gb = (size_t)(n0 + r)*CC + kt*64 + c*8;
            CP16(sb +         phys, Ah + ga);
            CP16(sb + 16384 + phys, Al + ga);
            CP16(sb + 32768 + phys, Bh + gb);
            CP16(sb + 49152 + phys, Bl + gb);
        }
        CP_COMMIT();
    };

    load_stage(0, 0);

    int ahalf = lane >> 4;
    int bhalf = (lane >> 3) & 1;
    int arow = wm*64 + (lane & 15);
    int brow = wn*32 + ((lane >> 4) << 3) + (lane & 7);

    for (int kt = 0; kt < NKT; kt++) {
        if (kt + 1 < NKT) { load_stage(kt + 1, (kt + 1) & 1); CP_WAIT(1); }
        else              { CP_WAIT(0); }
        __syncthreads();

        uint32_t sb = sbase + (uint32_t)(kt & 1) * GSTG;
#pragma unroll
        for (int kk = 0; kk < 4; kk++) {
            uint32_t aswz = (uint32_t)(((2*kk + ahalf) ^ (arow & 7)) << 4);
            uint32_t bswz = (uint32_t)(((2*kk + bhalf) ^ (brow & 7)) << 4);
            uint32_t ah4[4][4], al4[4][4], bh4[2][4], bl4[2][4];
#pragma unroll
            for (int mf = 0; mf < 4; mf++) {
                uint32_t off = (uint32_t)((arow + mf*16) * 128) + aswz;
                ldm4(ah4[mf], sb + off);
                ldm4(al4[mf], sb + 16384 + off);
            }
#pragma unroll
            for (int nh = 0; nh < 2; nh++) {
                uint32_t off = (uint32_t)((brow + nh*16) * 128) + bswz;
                ldm4(bh4[nh], sb + 32768 + off);
                ldm4(bl4[nh], sb + 49152 + off);
            }
#pragma unroll
            for (int mf = 0; mf < 4; mf++)
#pragma unroll
                for (int nf = 0; nf < 4; nf++) {
                    const uint32_t* ph = bh4[nf >> 1] + (nf & 1)*2;
                    const uint32_t* pl = bl4[nf >> 1] + (nf & 1)*2;
                    mma_f32(acc[mf][nf], ah4[mf], ph);      // main
                    mma_f16(cac[mf][nf], ah4[mf], pl);      // corr 1
                    mma_f16(cac[mf][nf], al4[mf], ph);      // corr 2
                }
        }
        __syncthreads();
    }

    int g = lane >> 2, t2 = (lane & 3) * 2;
#pragma unroll
    for (int nf = 0; nf < 4; nf++) {
        int col = n0 + wn*32 + nf*8 + t2;
        float2 bb = *(const float2*)(bias + col);
#pragma unroll
        for (int mf = 0; mf < 4; mf++) {
            int m1 = m0 + wm*64 + mf*16 + g;
            float2 cl = h2f(cac[mf][nf][0]);
            float2 ch = h2f(cac[mf][nf][1]);
            float v0 = acc[mf][nf][0] + cl.x + bb.x, v1 = acc[mf][nf][1] + cl.y + bb.y;
            float v2 = acc[mf][nf][2] + ch.x + bb.x, v3 = acc[mf][nf][3] + ch.y + bb.y;
            if (MODE == 0) {
                int h = col >> 6, d = col & 63;
                int b1 = m1 >> 11, t1 = m1 & (TT - 1);
                size_t base = ((size_t)(b1*HH + h)*TT) * DD + d;
                split_st(outH, outL, base + (size_t)t1*DD,       v0*scale, v1*scale);
                split_st(outH, outL, base + (size_t)(t1 + 8)*DD, v2*scale, v3*scale);
            } else {
                *(float2*)(outF + (size_t)m1*CC + col)       = make_float2(v0, v1);
                *(float2*)(outF + (size_t)(m1 + 8)*CC + col) = make_float2(v2, v3);
            }
        }
    }
}

// ---------------------------------------------------------------------------
// Tensor-core causal flash attention, fp16x3 with f16-acc corrections.
// Block: 128 q-rows, 8 warps. k-tiles of 64, cp.async 2-stage. 96KB smem.
// ---------------------------------------------------------------------------
__global__ __launch_bounds__(256) void attn_mma()
{
    extern __shared__ char smraw[];
    const uint32_t sb = smem_u32(smraw);
    const uint32_t QH = 0, QL = 16384, ST = 32768, STSZ = 32768;

    int tid = threadIdx.x, lane = tid & 31, w = tid >> 5;
    int bh = blockIdx.y;
    int qt = (int)gridDim.x - 1 - (int)blockIdx.x;
    int q0 = qt * 128;
    int nkt = 2*qt + 2;

    const h16* Qh = g_qh + (size_t)bh*TT*DD;
    const h16* Ql = g_ql + (size_t)bh*TT*DD;
    const h16* Kh = g_kh + (size_t)bh*TT*DD;
    const h16* Kl = g_kl + (size_t)bh*TT*DD;
    const h16* Vh = g_vh + (size_t)bh*TT*DD;
    const h16* Vl = g_vl + (size_t)bh*TT*DD;

    auto load_kv = [&](int kt, int s) {
        uint32_t base = sb + ST + (uint32_t)s * STSZ;
        int k0 = kt * 64;
#pragma unroll
        for (int i = 0; i < 2; i++) {
            int id = tid + i*256;
            int r = id >> 3, c = id & 7;
            uint32_t phys = (uint32_t)(r*128 + ((c ^ (r & 7)) << 4));
            size_t gsrc = (size_t)(k0 + r)*DD + c*8;
            CP16(base +         phys, Kh + gsrc);
            CP16(base +  8192 + phys, Kl + gsrc);
            CP16(base + 16384 + phys, Vh + gsrc);
            CP16(base + 24576 + phys, Vl + gsrc);
        }
        CP_COMMIT();
    };

#pragma unroll
    for (int m = 0; m < 2; m++)
#pragma unroll
        for (int i = 0; i < 4; i++) {
            int id = tid + i*256;
            int r = id >> 3, c = id & 7;
            uint32_t dst = sb + (m ? QL : QH) + (uint32_t)(r*128 + ((c ^ (r & 7)) << 4));
            const h16* src = (m ? Ql : Qh) + (size_t)(q0 + r)*DD + c*8;
            CP16(dst, src);
        }
    CP_COMMIT();
    load_kv(0, 0);

    CP_WAIT(1);
    __syncthreads();

    uint32_t qfh[4][4], qfl[4][4];
    int arow = w*16 + (lane & 15), ahalf = lane >> 4;
#pragma unroll
    for (int kk = 0; kk < 4; kk++) {
        uint32_t off = (uint32_t)(arow*128 + (((2*kk + ahalf) ^ (arow & 7)) << 4));
        ldm4(qfh[kk], sb + QH + off);
        ldm4(qfl[kk], sb + QL + off);
    }

    float oacc[8][4] = {};
    float mrow0 = -1e30f, mrow1 = -1e30f;
    float lsum0 = 0.f, lsum1 = 0.f;

    int g = lane >> 2, t2 = (lane & 3) * 2;
    int r0g = q0 + 16*w + g, r1g = r0g + 8;
    int bhalf = (lane >> 3) & 1;
    int vi = lane >> 3, vr = lane & 7;

    for (int kt = 0; kt < nkt; kt++) {
        if (kt + 1 < nkt) { load_kv(kt + 1, (kt + 1) & 1); CP_WAIT(1); }
        else              { CP_WAIT(0); }
        __syncthreads();

        int k0 = kt * 64;
        if (k0 <= q0 + 16*w + 15) {
            uint32_t st = sb + ST + (uint32_t)(kt & 1) * STSZ;

            // ---- S = Q K^T: main f32, corrections f16-acc ----
            float sacc[8][4] = {};
            uint32_t scorr[8][2] = {};
#pragma unroll
            for (int kk = 0; kk < 4; kk++) {
#pragma unroll
                for (int ng = 0; ng < 4; ng++) {
                    int brow = ng*16 + ((lane >> 4) << 3) + (lane & 7);
                    uint32_t off = (uint32_t)(brow*128 + (((2*kk + bhalf) ^ (brow & 7)) << 4));
                    uint32_t kh4[4], kl4[4];
                    ldm4(kh4, st + off);
                    ldm4(kl4, st + 8192 + off);
                    mma_f32(sacc[2*ng],    qfh[kk], kh4);
                    mma_f16(scorr[2*ng],   qfh[kk], kl4);
                    mma_f16(scorr[2*ng],   qfl[kk], kh4);
                    mma_f32(sacc[2*ng+1],  qfh[kk], kh4 + 2);
                    mma_f16(scorr[2*ng+1], qfh[kk], kl4 + 2);
                    mma_f16(scorr[2*ng+1], qfl[kk], kh4 + 2);
                }
            }
#pragma unroll
            for (int j = 0; j < 8; j++) {
                float2 cl = h2f(scorr[j][0]), ch = h2f(scorr[j][1]);
                sacc[j][0] += cl.x; sacc[j][1] += cl.y;
                sacc[j][2] += ch.x; sacc[j][3] += ch.y;
            }

            // ---- causal mask ----
            if (k0 + 63 > r0g) {
#pragma unroll
                for (int j = 0; j < 8; j++) {
                    int col = k0 + 8*j + t2;
                    if (col     > r0g) sacc[j][0] = -1e30f;
                    if (col + 1 > r0g) sacc[j][1] = -1e30f;
                    if (col     > r1g) sacc[j][2] = -1e30f;
                    if (col + 1 > r1g) sacc[j][3] = -1e30f;
                }
            }

            // ---- online softmax ----
            float tm0 = -1e30f, tm1 = -1e30f;
#pragma unroll
            for (int j = 0; j < 8; j++) {
                tm0 = fmaxf(tm0, fmaxf(sacc[j][0], sacc[j][1]));
                tm1 = fmaxf(tm1, fmaxf(sacc[j][2], sacc[j][3]));
            }
            tm0 = fmaxf(tm0, __shfl_xor_sync(0xffffffffu, tm0, 1));
            tm0 = fmaxf(tm0, __shfl_xor_sync(0xffffffffu, tm0, 2));
            tm1 = fmaxf(tm1, __shfl_xor_sync(0xffffffffu, tm1, 1));
            tm1 = fmaxf(tm1, __shfl_xor_sync(0xffffffffu, tm1, 2));
            float mn0 = fmaxf(mrow0, tm0), mn1 = fmaxf(mrow1, tm1);
            float c0 = __expf(mrow0 - mn0), c1 = __expf(mrow1 - mn1);
            mrow0 = mn0; mrow1 = mn1;

            float ps0 = 0.f, ps1 = 0.f;
            uint32_t pfh[4][4], pfl[4][4];
#pragma unroll
            for (int kc = 0; kc < 4; kc++) {
#pragma unroll
                for (int jj = 0; jj < 2; jj++) {
                    int j = 2*kc + jj;
                    float p0 = __expf(sacc[j][0] - mn0);
                    float p1 = __expf(sacc[j][1] - mn0);
                    float p2 = __expf(sacc[j][2] - mn1);
                    float p3 = __expf(sacc[j][3] - mn1);
                    ps0 += p0 + p1; ps1 += p2 + p3;
                    float h0 = __half2float(__float2half_rn(p0));
                    float h1 = __half2float(__float2half_rn(p1));
                    float h2 = __half2float(__float2half_rn(p2));
                    float h3 = __half2float(__float2half_rn(p3));
                    pfh[kc][2*jj]   = pk2h(h0, h1);
                    pfh[kc][2*jj+1] = pk2h(h2, h3);
                    pfl[kc][2*jj]   = pk2h(p0 - h0, p1 - h1);
                    pfl[kc][2*jj+1] = pk2h(p2 - h2, p3 - h3);
                }
            }
            lsum0 = lsum0 * c0 + ps0;
            lsum1 = lsum1 * c1 + ps1;
#pragma unroll
            for (int j = 0; j < 8; j++) {
                oacc[j][0] *= c0; oacc[j][1] *= c0;
                oacc[j][2] *= c1; oacc[j][3] *= c1;
            }

            // ---- O += P V: main f32, fresh per-tile f16 corrections ----
            uint32_t ocorr[8][2] = {};
#pragma unroll
            for (int kc = 0; kc < 4; kc++) {
#pragma unroll
                for (int dg = 0; dg < 4; dg++) {
                    int key = kc*16 + 8*(vi & 1) + vr;
                    int dc = 2*dg + (vi >> 1);
                    uint32_t off = (uint32_t)(key*128 + ((dc ^ (key & 7)) << 4));
                    uint32_t vh4[4], vl4[4];
                    ldm4t(vh4, st + 16384 + off);
                    ldm4t(vl4, st + 24576 + off);
                    mma_f32(oacc[2*dg],    pfh[kc], vh4);
                    mma_f16(ocorr[2*dg],   pfh[kc], vl4);
                    mma_f16(ocorr[2*dg],   pfl[kc], vh4);
                    mma_f32(oacc[2*dg+1],  pfh[kc], vh4 + 2);
                    mma_f16(ocorr[2*dg+1], pfh[kc], vl4 + 2);
                    mma_f16(ocorr[2*dg+1], pfl[kc], vh4 + 2);
                }
            }
#pragma unroll
            for (int j = 0; j < 8; j++) {
                float2 cl = h2f(ocorr[j][0]), ch = h2f(ocorr[j][1]);
                oacc[j][0] += cl.x; oacc[j][1] += cl.y;
                oacc[j][2] += ch.x; oacc[j][3] += ch.y;
            }
        }
        __syncthreads();
    }

    lsum0 += __shfl_xor_sync(0xffffffffu, lsum0, 1);
    lsum0 += __shfl_xor_sync(0xffffffffu, lsum0, 2);
    lsum1 += __shfl_xor_sync(0xffffffffu, lsum1, 1);
    lsum1 += __shfl_xor_sync(0xffffffffu, lsum1, 2);
    float inv0 = 1.f / lsum0, inv1 = 1.f / lsum1;

    int b = bh >> 4, h = bh & 15;
    size_t row0 = (size_t)(b*TT + r0g) * CC + h*DD;
    size_t row1 = (size_t)(b*TT + r1g) * CC + h*DD;
#pragma unroll
    for (int j = 0; j < 8; j++) {
        int d = 8*j + t2;
        split_st(g_ah, g_al, row0 + d, oacc[j][0]*inv0, oacc[j][1]*inv0);
        split_st(g_ah, g_al, row1 + d, oacc[j][2]*inv1, oacc[j][3]*inv1);
    }
}

// ---------------------------------------------------------------------------
extern "C" void kernel_launch(void* const* d_in, const int* in_sizes, int n_in,
                              void* d_out, int out_size)
{
    (void)in_sizes; (void)n_in; (void)out_size;
    const float* x  = (const float*)d_in[0];
    const float* Wq = (const float*)d_in[1];
    const float* bq = (const float*)d_in[2];
    const float* Wk = (const float*)d_in[3];
    const float* bk = (const float*)d_in[4];
    const float* Wv = (const float*)d_in[5];
    const float* bv = (const float*)d_in[6];
    const float* Wo = (const float*)d_in[7];
    const float* bo = (const float*)d_in[8];
    float* out = (float*)d_out;

    h16 *xh, *xl, *ah, *al, *wh, *wl, *qh, *ql, *kh, *kl, *vh, *vl;
    cudaGetSymbolAddress((void**)&xh, g_xh);
    cudaGetSymbolAddress((void**)&xl, g_xl);
    cudaGetSymbolAddress((void**)&ah, g_ah);
    cudaGetSymbolAddress((void**)&al, g_al);
    cudaGetSymbolAddress((void**)&wh, g_wh);
    cudaGetSymbolAddress((void**)&wl, g_wl);
    cudaGetSymbolAddress((void**)&qh, g_qh);
    cudaGetSymbolAddress((void**)&ql, g_ql);
    cudaGetSymbolAddress((void**)&kh, g_kh);
    cudaGetSymbolAddress((void**)&kl, g_kl);
    cudaGetSymbolAddress((void**)&vh, g_vh);
    cudaGetSymbolAddress((void**)&vl, g_vl);

    // 1. split x
    split_kernel<<<(MM*CC/4)/256, 256>>>(x, xh, xl);

    // 2. transpose+split all 4 weights (one launch)
    tsplit_kernel<<<dim3(CC/32, CC/32, 4), dim3(32, 8)>>>(Wq, Wk, Wv, Wo, wh, wl);

    // 3. QKV projections -> split fp16 [B,H,T,D] (Q pre-scaled by 1/8)
    const int gsm = 2 * GSTG;  // 128 KB
    cudaFuncSetAttribute(gemm_f16x3<0>, cudaFuncAttributeMaxDynamicSharedMemorySize, gsm);
    cudaFuncSetAttribute(gemm_f16x3<1>, cudaFuncAttributeMaxDynamicSharedMemorySize, gsm);
    dim3 ggrid(CC/128, MM/128);   // (8, 32)
    gemm_f16x3<0><<<ggrid, 256, gsm>>>(xh, xl, wh + 0*CC*CC, wl + 0*CC*CC, bq,
                                       nullptr, qh, ql, 0.125f);
    gemm_f16x3<0><<<ggrid, 256, gsm>>>(xh, xl, wh + 1*CC*CC, wl + 1*CC*CC, bk,
                                       nullptr, kh, kl, 1.0f);
    gemm_f16x3<0><<<ggrid, 256, gsm>>>(xh, xl, wh + 2*CC*CC, wl + 2*CC*CC, bv,
                                       nullptr, vh, vl, 1.0f);

    // 4. tensor-core flash attention
    const int asm_sz = 98304;
    cudaFuncSetAttribute(attn_mma, cudaFuncAttributeMaxDynamicSharedMemorySize, asm_sz);
    attn_mma<<<dim3(TT/128, BB*HH), 256, asm_sz>>>();

    // 5. output projection -> d_out (fp32)
    gemm_f16x3<1><<<ggrid, 256, gsm>>>(ah, al, wh + 3*CC*CC, wl + 3*CC*CC, bo,
                                       out, nullptr, nullptr, 1.0f);
}

// round 9
// speedup vs baseline: 1.0318x; 1.0318x over previous
#include <cuda_runtime.h>
#include <cuda_fp16.h>
#include <cstdint>

// B=2, T=2048, C=1024, H=16, D=64, causal MHA, fp32 in/out.
#define BB 2
#define TT 2048
#define CC 1024
#define HH 16
#define DD 64
#define MM (BB*TT)

typedef __half h16;

// ---------------- scratch (allocation-free) ----------------
__device__ h16 g_xh[MM*CC], g_xl[MM*CC];
__device__ h16 g_ah[MM*CC], g_al[MM*CC];
__device__ h16 g_wh[4*CC*CC], g_wl[4*CC*CC];   // [Wq|Wk|Wv|Wo] transposed [n][k]
__device__ h16 g_qh[BB*HH*TT*DD], g_ql[BB*HH*TT*DD];
__device__ h16 g_kh[BB*HH*TT*DD], g_kl[BB*HH*TT*DD];
__device__ h16 g_vh[BB*HH*TT*DD], g_vl[BB*HH*TT*DD];

// ---------------- helpers (sm_80-baseline PTX only) ----------------
__device__ __forceinline__ uint32_t smem_u32(const void* p) {
    return (uint32_t)__cvta_generic_to_shared(p);
}

#define CP16(dst, src) \
    asm volatile("cp.async.cg.shared.global [%0], [%1], 16;" :: "r"(dst), "l"(src) : "memory")
#define CP_COMMIT() asm volatile("cp.async.commit_group;" ::: "memory")
#define CP_WAIT(n)  asm volatile("cp.async.wait_group %0;" :: "n"(n) : "memory")

__device__ __forceinline__ void ldm4(uint32_t* r, uint32_t a) {
    asm volatile("ldmatrix.sync.aligned.m8n8.x4.shared.b16 {%0,%1,%2,%3}, [%4];"
                 : "=r"(r[0]), "=r"(r[1]), "=r"(r[2]), "=r"(r[3]) : "r"(a));
}
__device__ __forceinline__ void ldm4t(uint32_t* r, uint32_t a) {
    asm volatile("ldmatrix.sync.aligned.m8n8.x4.trans.shared.b16 {%0,%1,%2,%3}, [%4];"
                 : "=r"(r[0]), "=r"(r[1]), "=r"(r[2]), "=r"(r[3]) : "r"(a));
}
__device__ __forceinline__ void mma_f32(float* d, const uint32_t* a, const uint32_t* b) {
    asm volatile("mma.sync.aligned.m16n8k16.row.col.f32.f16.f16.f32 "
                 "{%0,%1,%2,%3}, {%4,%5,%6,%7}, {%8,%9}, {%0,%1,%2,%3};"
                 : "+f"(d[0]), "+f"(d[1]), "+f"(d[2]), "+f"(d[3])
                 : "r"(a[0]), "r"(a[1]), "r"(a[2]), "r"(a[3]), "r"(b[0]), "r"(b[1]));
}

__device__ __forceinline__ float2 h2f(uint32_t u) {
    __half2 h = *reinterpret_cast<__half2*>(&u);
    return __half22float2(h);
}
__device__ __forceinline__ uint32_t pk2h(float a, float b) {
    __half2 t = __floats2half2_rn(a, b);
    return *reinterpret_cast<uint32_t*>(&t);
}
__device__ __forceinline__ void split_st(h16* hi, h16* lo, size_t off, float a, float b) {
    uint32_t hp = pk2h(a, b);
    float2 back = h2f(hp);
    *(uint32_t*)(hi + off) = hp;
    *(uint32_t*)(lo + off) = pk2h(a - back.x, b - back.y);
}

// ---------------------------------------------------------------------------
__global__ void split_kernel(const float* __restrict__ x,
                             h16* __restrict__ hi, h16* __restrict__ lo) {
    int i = blockIdx.x * blockDim.x + threadIdx.x;
    float4 v = ((const float4*)x)[i];
    split_st(hi, lo, 4*(size_t)i,     v.x, v.y);
    split_st(hi, lo, 4*(size_t)i + 2, v.z, v.w);
}

// ---------------------------------------------------------------------------
__global__ void tsplit_kernel(const float* __restrict__ W0, const float* __restrict__ W1,
                              const float* __restrict__ W2, const float* __restrict__ W3,
                              h16* __restrict__ hi, h16* __restrict__ lo) {
    __shared__ float t[32][33];
    int tx = threadIdx.x, ty = threadIdx.y;          // (32, 8)
    int n0 = blockIdx.x * 32, k0 = blockIdx.y * 32;
    int z = blockIdx.z;
    const float* W = (z == 0) ? W0 : (z == 1) ? W1 : (z == 2) ? W2 : W3;
    h16* hz = hi + (size_t)z * CC * CC;
    h16* lz = lo + (size_t)z * CC * CC;
#pragma unroll
    for (int i = 0; i < 4; i++)
        t[ty + 8*i][tx] = W[(size_t)(k0 + ty + 8*i) * CC + n0 + tx];
    __syncthreads();
#pragma unroll
    for (int i = 0; i < 4; i++) {
        float v = t[tx][ty + 8*i];
        __half h = __float2half_rn(v);
        size_t o = (size_t)(n0 + ty + 8*i) * CC + k0 + tx;
        hz[o] = h;
        lz[o] = __float2half_rn(v - __half2float(h));
    }
}

// ---------------------------------------------------------------------------
// fp16x3 GEMM (uniform f32-acc), R4 structure: 128x128 tile, K-chunk 64,
// 2-stage cp.async (128KB), 8 warps (64x32 each).
// MODE 0: fused QKV — grid.x covers N=3072; per-section bias/scale/dst,
//         split-fp16 output remapped to [B,H,T,D].
// MODE 1: single GEMM (Wo), plain fp32 [M,N] output.
// ---------------------------------------------------------------------------
#define GSTG 65536
#define NKT  16

template<int MODE>
__global__ __launch_bounds__(256) void gemm_f16x3(
    const h16* __restrict__ Ah, const h16* __restrict__ Al,
    const h16* __restrict__ Bh, const h16* __restrict__ Bl,
    const float* __restrict__ bias0, const float* __restrict__ bias1,
    const float* __restrict__ bias2,
    float* __restrict__ outF,
    h16* __restrict__ o0h, h16* __restrict__ o0l,
    h16* __restrict__ o1h, h16* __restrict__ o1l,
    h16* __restrict__ o2h, h16* __restrict__ o2l)
{
    extern __shared__ char smraw[];
    const uint32_t sbase = smem_u32(smraw);

    int tid = threadIdx.x, lane = tid & 31, wid = tid >> 5;
    int wm = wid & 1, wn = wid >> 1;
    int m0 = blockIdx.y << 7, n0 = blockIdx.x << 7;

    // per-section selection (constant per CTA; section = n0 >> 10)
    const float* bias = bias0;
    h16 *oh = o0h, *ol = o0l;
    float scale = 1.0f;
    if (MODE == 0) {
        int sec = n0 >> 10;
        bias = (sec == 0) ? bias0 : (sec == 1) ? bias1 : bias2;
        oh   = (sec == 0) ? o0h   : (sec == 1) ? o1h   : o2h;
        ol   = (sec == 0) ? o0l   : (sec == 1) ? o1l   : o2l;
        scale = (sec == 0) ? 0.125f : 1.0f;
    }

    float acc[4][4][4] = {};

    auto load_stage = [&](int kt, int s) {
        uint32_t sb = sbase + (uint32_t)s * GSTG;
#pragma unroll
        for (int i = 0; i < 4; i++) {
            int id = tid + i*256;
            int r = id >> 3, c = id & 7;
            uint32_t phys = (uint32_t)(r*128 + ((c ^ (r & 7)) << 4));
            size_t ga = (size_t)(m0 + r)*CC + kt*64 + c*8;
            size_t gb = (size_t)(n0 + r)*CC + kt*64 + c*8;
            CP16(sb +         phys, Ah + ga);
            CP16(sb + 16384 + phys, Al + ga);
            CP16(sb + 32768 + phys, Bh + gb);
            CP16(sb + 49152 + phys, Bl + gb);
        }
        CP_COMMIT();
    };

    load_stage(0, 0);

    int ahalf = lane >> 4;
    int bhalf = (lane >> 3) & 1;
    int arow = wm*64 + (lane & 15);
    int brow = wn*32 + ((lane >> 4) << 3) + (lane & 7);

    for (int kt = 0; kt < NKT; kt++) {
        if (kt + 1 < NKT) { load_stage(kt + 1, (kt + 1) & 1); CP_WAIT(1); }
        else              { CP_WAIT(0); }
        __syncthreads();

        uint32_t sb = sbase + (uint32_t)(kt & 1) * GSTG;
#pragma unroll
        for (int kk = 0; kk < 4; kk++) {
            uint32_t aswz = (uint32_t)(((2*kk + ahalf) ^ (arow & 7)) << 4);
            uint32_t bswz = (uint32_t)(((2*kk + bhalf) ^ (brow & 7)) << 4);
            uint32_t ah4[4][4], al4[4][4], bh4[2][4], bl4[2][4];
#pragma unroll
            for (int mf = 0; mf < 4; mf++) {
                uint32_t off = (uint32_t)((arow + mf*16) * 128) + aswz;
                ldm4(ah4[mf], sb + off);
                ldm4(al4[mf], sb + 16384 + off);
            }
#pragma unroll
            for (int nh = 0; nh < 2; nh++) {
                uint32_t off = (uint32_t)((brow + nh*16) * 128) + bswz;
                ldm4(bh4[nh], sb + 32768 + off);
                ldm4(bl4[nh], sb + 49152 + off);
            }
#pragma unroll
            for (int mf = 0; mf < 4; mf++)
#pragma unroll
                for (int nf = 0; nf < 4; nf++) {
                    const uint32_t* ph = bh4[nf >> 1] + (nf & 1)*2;
                    const uint32_t* pl = bl4[nf >> 1] + (nf & 1)*2;
                    mma_f32(acc[mf][nf], ah4[mf], ph);
                    mma_f32(acc[mf][nf], ah4[mf], pl);
                    mma_f32(acc[mf][nf], al4[mf], ph);
                }
        }
        __syncthreads();
    }

    int g = lane >> 2, t2 = (lane & 3) * 2;
#pragma unroll
    for (int nf = 0; nf < 4; nf++) {
        int col = n0 + wn*32 + nf*8 + t2;
        int lc = col & (CC - 1);                      // col within section
        float2 bb = *(const float2*)(bias + lc);
#pragma unroll
        for (int mf = 0; mf < 4; mf++) {
            int m1 = m0 + wm*64 + mf*16 + g;
            float v0 = acc[mf][nf][0] + bb.x, v1 = acc[mf][nf][1] + bb.y;
            float v2 = acc[mf][nf][2] + bb.x, v3 = acc[mf][nf][3] + bb.y;
            if (MODE == 0) {
                int h = lc >> 6, d = lc & 63;
                int b1 = m1 >> 11, t1 = m1 & (TT - 1);
                size_t base = ((size_t)(b1*HH + h)*TT) * DD + d;
                split_st(oh, ol, base + (size_t)t1*DD,       v0*scale, v1*scale);
                split_st(oh, ol, base + (size_t)(t1 + 8)*DD, v2*scale, v3*scale);
            } else {
                *(float2*)(outF + (size_t)m1*CC + col)       = make_float2(v0, v1);
                *(float2*)(outF + (size_t)(m1 + 8)*CC + col) = make_float2(v2, v3);
            }
        }
    }
}

// ---------------------------------------------------------------------------
// Tensor-core causal flash attention, fp16x3, uniform f32 accumulate.
// Block: 128 q-rows, 8 warps. k-tiles of 64, cp.async 2-stage. 96KB smem.
// ---------------------------------------------------------------------------
__global__ __launch_bounds__(256) void attn_mma()
{
    extern __shared__ char smraw[];
    const uint32_t sb = smem_u32(smraw);
    const uint32_t QH = 0, QL = 16384, ST = 32768, STSZ = 32768;

    int tid = threadIdx.x, lane = tid & 31, w = tid >> 5;
    int bh = blockIdx.y;
    int qt = (int)gridDim.x - 1 - (int)blockIdx.x;
    int q0 = qt * 128;
    int nkt = 2*qt + 2;

    const h16* Qh = g_qh + (size_t)bh*TT*DD;
    const h16* Ql = g_ql + (size_t)bh*TT*DD;
    const h16* Kh = g_kh + (size_t)bh*TT*DD;
    const h16* Kl = g_kl + (size_t)bh*TT*DD;
    const h16* Vh = g_vh + (size_t)bh*TT*DD;
    const h16* Vl = g_vl + (size_t)bh*TT*DD;

    auto load_kv = [&](int kt, int s) {
        uint32_t base = sb + ST + (uint32_t)s * STSZ;
        int k0 = kt * 64;
#pragma unroll
        for (int i = 0; i < 2; i++) {
            int id = tid + i*256;
            int r = id >> 3, c = id & 7;
            uint32_t phys = (uint32_t)(r*128 + ((c ^ (r & 7)) << 4));
            size_t gsrc = (size_t)(k0 + r)*DD + c*8;
            CP16(base +         phys, Kh + gsrc);
            CP16(base +  8192 + phys, Kl + gsrc);
            CP16(base + 16384 + phys, Vh + gsrc);
            CP16(base + 24576 + phys, Vl + gsrc);
        }
        CP_COMMIT();
    };

#pragma unroll
    for (int m = 0; m < 2; m++)
#pragma unroll
        for (int i = 0; i < 4; i++) {
            int id = tid + i*256;
            int r = id >> 3, c = id & 7;
            uint32_t dst = sb + (m ? QL : QH) + (uint32_t)(r*128 + ((c ^ (r & 7)) << 4));
            const h16* src = (m ? Ql : Qh) + (size_t)(q0 + r)*DD + c*8;
            CP16(dst, src);
        }
    CP_COMMIT();
    load_kv(0, 0);

    CP_WAIT(1);
    __syncthreads();

    uint32_t qfh[4][4], qfl[4][4];
    int arow = w*16 + (lane & 15), ahalf = lane >> 4;
#pragma unroll
    for (int kk = 0; kk < 4; kk++) {
        uint32_t off = (uint32_t)(arow*128 + (((2*kk + ahalf) ^ (arow & 7)) << 4));
        ldm4(qfh[kk], sb + QH + off);
        ldm4(qfl[kk], sb + QL + off);
    }

    float oacc[8][4] = {};
    float mrow0 = -1e30f, mrow1 = -1e30f;
    float lsum0 = 0.f, lsum1 = 0.f;

    int g = lane >> 2, t2 = (lane & 3) * 2;
    int r0g = q0 + 16*w + g, r1g = r0g + 8;
    int bhalf = (lane >> 3) & 1;
    int vi = lane >> 3, vr = lane & 7;

    for (int kt = 0; kt < nkt; kt++) {
        if (kt + 1 < nkt) { load_kv(kt + 1, (kt + 1) & 1); CP_WAIT(1); }
        else              { CP_WAIT(0); }
        __syncthreads();

        int k0 = kt * 64;
        if (k0 <= q0 + 16*w + 15) {
            uint32_t st = sb + ST + (uint32_t)(kt & 1) * STSZ;

            float sacc[8][4] = {};
#pragma unroll
            for (int kk = 0; kk < 4; kk++) {
#pragma unroll
                for (int ng = 0; ng < 4; ng++) {
                    int brow = ng*16 + ((lane >> 4) << 3) + (lane & 7);
                    uint32_t off = (uint32_t)(brow*128 + (((2*kk + bhalf) ^ (brow & 7)) << 4));
                    uint32_t kh4[4], kl4[4];
                    ldm4(kh4, st + off);
                    ldm4(kl4, st + 8192 + off);
                    mma_f32(sacc[2*ng],   qfh[kk], kh4);
                    mma_f32(sacc[2*ng],   qfh[kk], kl4);
                    mma_f32(sacc[2*ng],   qfl[kk], kh4);
                    mma_f32(sacc[2*ng+1], qfh[kk], kh4 + 2);
                    mma_f32(sacc[2*ng+1], qfh[kk], kl4 + 2);
                    mma_f32(sacc[2*ng+1], qfl[kk], kh4 + 2);
                }
            }

            if (k0 + 63 > r0g) {
#pragma unroll
                for (int j = 0; j < 8; j++) {
                    int col = k0 + 8*j + t2;
                    if (col     > r0g) sacc[j][0] = -1e30f;
                    if (col + 1 > r0g) sacc[j][1] = -1e30f;
                    if (col     > r1g) sacc[j][2] = -1e30f;
                    if (col + 1 > r1g) sacc[j][3] = -1e30f;
                }
            }

            float tm0 = -1e30f, tm1 = -1e30f;
#pragma unroll
            for (int j = 0; j < 8; j++) {
                tm0 = fmaxf(tm0, fmaxf(sacc[j][0], sacc[j][1]));
                tm1 = fmaxf(tm1, fmaxf(sacc[j][2], sacc[j][3]));
            }
            tm0 = fmaxf(tm0, __shfl_xor_sync(0xffffffffu, tm0, 1));
            tm0 = fmaxf(tm0, __shfl_xor_sync(0xffffffffu, tm0, 2));
            tm1 = fmaxf(tm1, __shfl_xor_sync(0xffffffffu, tm1, 1));
            tm1 = fmaxf(tm1, __shfl_xor_sync(0xffffffffu, tm1, 2));
            float mn0 = fmaxf(mrow0, tm0), mn1 = fmaxf(mrow1, tm1);
            float c0 = __expf(mrow0 - mn0), c1 = __expf(mrow1 - mn1);
            mrow0 = mn0; mrow1 = mn1;

            float ps0 = 0.f, ps1 = 0.f;
            uint32_t pfh[4][4], pfl[4][4];
#pragma unroll
            for (int kc = 0; kc < 4; kc++) {
#pragma unroll
                for (int jj = 0; jj < 2; jj++) {
                    int j = 2*kc + jj;
                    float p0 = __expf(sacc[j][0] - mn0);
                    float p1 = __expf(sacc[j][1] - mn0);
                    float p2 = __expf(sacc[j][2] - mn1);
                    float p3 = __expf(sacc[j][3] - mn1);
                    ps0 += p0 + p1; ps1 += p2 + p3;
                    uint32_t hp01 = pk2h(p0, p1);
                    uint32_t hp23 = pk2h(p2, p3);
                    float2 b01 = h2f(hp01), b23 = h2f(hp23);
                    pfh[kc][2*jj]   = hp01;
                    pfh[kc][2*jj+1] = hp23;
                    pfl[kc][2*jj]   = pk2h(p0 - b01.x, p1 - b01.y);
                    pfl[kc][2*jj+1] = pk2h(p2 - b23.x, p3 - b23.y);
                }
            }
            lsum0 = lsum0 * c0 + ps0;
            lsum1 = lsum1 * c1 + ps1;
#pragma unroll
            for (int j = 0; j < 8; j++) {
                oacc[j][0] *= c0; oacc[j][1] *= c0;
                oacc[j][2] *= c1; oacc[j][3] *= c1;
            }

#pragma unroll
            for (int kc = 0; kc < 4; kc++) {
#pragma unroll
                for (int dg = 0; dg < 4; dg++) {
                    int key = kc*16 + 8*(vi & 1) + vr;
                    int dc = 2*dg + (vi >> 1);
                    uint32_t off = (uint32_t)(key*128 + ((dc ^ (key & 7)) << 4));
                    uint32_t vh4[4], vl4[4];
                    ldm4t(vh4, st + 16384 + off);
                    ldm4t(vl4, st + 24576 + off);
                    mma_f32(oacc[2*dg],   pfh[kc], vh4);
                    mma_f32(oacc[2*dg],   pfh[kc], vl4);
                    mma_f32(oacc[2*dg],   pfl[kc], vh4);
                    mma_f32(oacc[2*dg+1], pfh[kc], vh4 + 2);
                    mma_f32(oacc[2*dg+1], pfh[kc], vl4 + 2);
                    mma_f32(oacc[2*dg+1], pfl[kc], vh4 + 2);
                }
            }
        }
        __syncthreads();
    }

    lsum0 += __shfl_xor_sync(0xffffffffu, lsum0, 1);
    lsum0 += __shfl_xor_sync(0xffffffffu, lsum0, 2);
    lsum1 += __shfl_xor_sync(0xffffffffu, lsum1, 1);
    lsum1 += __shfl_xor_sync(0xffffffffu, lsum1, 2);
    float inv0 = 1.f / lsum0, inv1 = 1.f / lsum1;

    int b = bh >> 4, h = bh & 15;
    size_t row0 = (size_t)(b*TT + r0g) * CC + h*DD;
    size_t row1 = (size_t)(b*TT + r1g) * CC + h*DD;
#pragma unroll
    for (int j = 0; j < 8; j++) {
        int d = 8*j + t2;
        split_st(g_ah, g_al, row0 + d, oacc[j][0]*inv0, oacc[j][1]*inv0);
        split_st(g_ah, g_al, row1 + d, oacc[j][2]*inv1, oacc[j][3]*inv1);
    }
}

// ---------------------------------------------------------------------------
extern "C" void kernel_launch(void* const* d_in, const int* in_sizes, int n_in,
                              void* d_out, int out_size)
{
    (void)in_sizes; (void)n_in; (void)out_size;
    const float* x  = (const float*)d_in[0];
    const float* Wq = (const float*)d_in[1];
    const float* bq = (const float*)d_in[2];
    const float* Wk = (const float*)d_in[3];
    const float* bk = (const float*)d_in[4];
    const float* Wv = (const float*)d_in[5];
    const float* bv = (const float*)d_in[6];
    const float* Wo = (const float*)d_in[7];
    const float* bo = (const float*)d_in[8];
    float* out = (float*)d_out;

    h16 *xh, *xl, *ah, *al, *wh, *wl, *qh, *ql, *kh, *kl, *vh, *vl;
    cudaGetSymbolAddress((void**)&xh, g_xh);
    cudaGetSymbolAddress((void**)&xl, g_xl);
    cudaGetSymbolAddress((void**)&ah, g_ah);
    cudaGetSymbolAddress((void**)&al, g_al);
    cudaGetSymbolAddress((void**)&wh, g_wh);
    cudaGetSymbolAddress((void**)&wl, g_wl);
    cudaGetSymbolAddress((void**)&qh, g_qh);
    cudaGetSymbolAddress((void**)&ql, g_ql);
    cudaGetSymbolAddress((void**)&kh, g_kh);
    cudaGetSymbolAddress((void**)&kl, g_kl);
    cudaGetSymbolAddress((void**)&vh, g_vh);
    cudaGetSymbolAddress((void**)&vl, g_vl);

    // 1. split x
    split_kernel<<<(MM*CC/4)/256, 256>>>(x, xh, xl);

    // 2. transpose+split all 4 weights (one launch) -> [Wq|Wk|Wv|Wo]^T [n][k]
    tsplit_kernel<<<dim3(CC/32, CC/32, 4), dim3(32, 8)>>>(Wq, Wk, Wv, Wo, wh, wl);

    // 3. fused QKV projection (N=3072) -> split fp16 [B,H,T,D] (Q scaled 1/8)
    const int gsm = 2 * GSTG;  // 128 KB
    cudaFuncSetAttribute(gemm_f16x3<0>, cudaFuncAttributeMaxDynamicSharedMemorySize, gsm);
    cudaFuncSetAttribute(gemm_f16x3<1>, cudaFuncAttributeMaxDynamicSharedMemorySize, gsm);
    gemm_f16x3<0><<<dim3(3*CC/128, MM/128), 256, gsm>>>(
        xh, xl, wh, wl, bq, bk, bv,
        nullptr, qh, ql, kh, kl, vh, vl);

    // 4. tensor-core flash attention
    const int asm_sz = 98304;
    cudaFuncSetAttribute(attn_mma, cudaFuncAttributeMaxDynamicSharedMemorySize, asm_sz);
    attn_mma<<<dim3(TT/128, BB*HH), 256, asm_sz>>>();

    // 5. output projection -> d_out (fp32)
    gemm_f16x3<1><<<dim3(CC/128, MM/128), 256, gsm>>>(
        ah, al, wh + (size_t)3*CC*CC, wl + (size_t)3*CC*CC, bo, nullptr, nullptr,
        out, nullptr, nullptr, nullptr, nullptr, nullptr, nullptr);
}

// round 10
// speedup vs baseline: 1.0323x; 1.0005x over previous
#include <cuda_runtime.h>
#include <cuda_fp16.h>
#include <cstdint>

// B=2, T=2048, C=1024, H=16, D=64, causal MHA, fp32 in/out.
#define BB 2
#define TT 2048
#define CC 1024
#define HH 16
#define DD 64
#define MM (BB*TT)

typedef __half h16;

// ---------------- scratch (allocation-free) ----------------
__device__ h16 g_xh[MM*CC], g_xl[MM*CC];
__device__ h16 g_ah[MM*CC], g_al[MM*CC];
__device__ h16 g_wh[4*CC*CC], g_wl[4*CC*CC];   // [Wq|Wk|Wv|Wo] transposed [n][k]
__device__ h16 g_qh[BB*HH*TT*DD], g_ql[BB*HH*TT*DD];
__device__ h16 g_kh[BB*HH*TT*DD], g_kl[BB*HH*TT*DD];
__device__ h16 g_vh[BB*HH*TT*DD], g_vl[BB*HH*TT*DD];

// ---------------- helpers (sm_80-baseline PTX only) ----------------
__device__ __forceinline__ uint32_t smem_u32(const void* p) {
    return (uint32_t)__cvta_generic_to_shared(p);
}

#define CP16(dst, src) \
    asm volatile("cp.async.cg.shared.global [%0], [%1], 16;" :: "r"(dst), "l"(src) : "memory")
#define CP_COMMIT() asm volatile("cp.async.commit_group;" ::: "memory")
#define CP_WAIT(n)  asm volatile("cp.async.wait_group %0;" :: "n"(n) : "memory")

__device__ __forceinline__ void ldm4(uint32_t* r, uint32_t a) {
    asm volatile("ldmatrix.sync.aligned.m8n8.x4.shared.b16 {%0,%1,%2,%3}, [%4];"
                 : "=r"(r[0]), "=r"(r[1]), "=r"(r[2]), "=r"(r[3]) : "r"(a));
}
__device__ __forceinline__ void ldm4t(uint32_t* r, uint32_t a) {
    asm volatile("ldmatrix.sync.aligned.m8n8.x4.trans.shared.b16 {%0,%1,%2,%3}, [%4];"
                 : "=r"(r[0]), "=r"(r[1]), "=r"(r[2]), "=r"(r[3]) : "r"(a));
}
__device__ __forceinline__ void mma_f32(float* d, const uint32_t* a, const uint32_t* b) {
    asm volatile("mma.sync.aligned.m16n8k16.row.col.f32.f16.f16.f32 "
                 "{%0,%1,%2,%3}, {%4,%5,%6,%7}, {%8,%9}, {%0,%1,%2,%3};"
                 : "+f"(d[0]), "+f"(d[1]), "+f"(d[2]), "+f"(d[3])
                 : "r"(a[0]), "r"(a[1]), "r"(a[2]), "r"(a[3]), "r"(b[0]), "r"(b[1]));
}

__device__ __forceinline__ float2 h2f(uint32_t u) {
    __half2 h = *reinterpret_cast<__half2*>(&u);
    return __half22float2(h);
}
__device__ __forceinline__ uint32_t pk2h(float a, float b) {
    __half2 t = __floats2half2_rn(a, b);
    return *reinterpret_cast<uint32_t*>(&t);
}
__device__ __forceinline__ void split_st(h16* hi, h16* lo, size_t off, float a, float b) {
    uint32_t hp = pk2h(a, b);
    float2 back = h2f(hp);
    *(uint32_t*)(hi + off) = hp;
    *(uint32_t*)(lo + off) = pk2h(a - back.x, b - back.y);
}

// ---------------------------------------------------------------------------
__global__ void split_kernel(const float* __restrict__ x,
                             h16* __restrict__ hi, h16* __restrict__ lo) {
    int i = blockIdx.x * blockDim.x + threadIdx.x;
    float4 v = ((const float4*)x)[i];
    split_st(hi, lo, 4*(size_t)i,     v.x, v.y);
    split_st(hi, lo, 4*(size_t)i + 2, v.z, v.w);
}

// ---------------------------------------------------------------------------
__global__ void tsplit_kernel(const float* __restrict__ W0, const float* __restrict__ W1,
                              const float* __restrict__ W2, const float* __restrict__ W3,
                              h16* __restrict__ hi, h16* __restrict__ lo) {
    __shared__ float t[32][33];
    int tx = threadIdx.x, ty = threadIdx.y;          // (32, 8)
    int n0 = blockIdx.x * 32, k0 = blockIdx.y * 32;
    int z = blockIdx.z;
    const float* W = (z == 0) ? W0 : (z == 1) ? W1 : (z == 2) ? W2 : W3;
    h16* hz = hi + (size_t)z * CC * CC;
    h16* lz = lo + (size_t)z * CC * CC;
#pragma unroll
    for (int i = 0; i < 4; i++)
        t[ty + 8*i][tx] = W[(size_t)(k0 + ty + 8*i) * CC + n0 + tx];
    __syncthreads();
#pragma unroll
    for (int i = 0; i < 4; i++) {
        float v = t[tx][ty + 8*i];
        __half h = __float2half_rn(v);
        size_t o = (size_t)(n0 + ty + 8*i) * CC + k0 + tx;
        hz[o] = h;
        lz[o] = __float2half_rn(v - __half2float(h));
    }
}

// ---------------------------------------------------------------------------
// fp16x3 GEMM (uniform f32-acc): 128x128 tile, K-chunk 64, 2-stage cp.async.
// MODE 0: fused QKV (grid.x covers N=3072), split-fp16 out to [B,H,T,D].
// MODE 1: single GEMM (Wo), fp32 [M,N].
// ---------------------------------------------------------------------------
#define GSTG 65536
#define NKT  16

template<int MODE>
__global__ __launch_bounds__(256) void gemm_f16x3(
    const h16* __restrict__ Ah, const h16* __restrict__ Al,
    const h16* __restrict__ Bh, const h16* __restrict__ Bl,
    const float* __restrict__ bias0, const float* __restrict__ bias1,
    const float* __restrict__ bias2,
    float* __restrict__ outF,
    h16* __restrict__ o0h, h16* __restrict__ o0l,
    h16* __restrict__ o1h, h16* __restrict__ o1l,
    h16* __restrict__ o2h, h16* __restrict__ o2l)
{
    extern __shared__ char smraw[];
    const uint32_t sbase = smem_u32(smraw);

    int tid = threadIdx.x, lane = tid & 31, wid = tid >> 5;
    int wm = wid & 1, wn = wid >> 1;
    int m0 = blockIdx.y << 7, n0 = blockIdx.x << 7;

    const float* bias = bias0;
    h16 *oh = o0h, *ol = o0l;
    float scale = 1.0f;
    if (MODE == 0) {
        int sec = n0 >> 10;
        bias = (sec == 0) ? bias0 : (sec == 1) ? bias1 : bias2;
        oh   = (sec == 0) ? o0h   : (sec == 1) ? o1h   : o2h;
        ol   = (sec == 0) ? o0l   : (sec == 1) ? o1l   : o2l;
        scale = (sec == 0) ? 0.125f : 1.0f;
    }

    float acc[4][4][4] = {};

    auto load_stage = [&](int kt, int s) {
        uint32_t sb = sbase + (uint32_t)s * GSTG;
#pragma unroll
        for (int i = 0; i < 4; i++) {
            int id = tid + i*256;
            int r = id >> 3, c = id & 7;
            uint32_t phys = (uint32_t)(r*128 + ((c ^ (r & 7)) << 4));
            size_t ga = (size_t)(m0 + r)*CC + kt*64 + c*8;
            size_t gb = (size_t)(n0 + r)*CC + kt*64 + c*8;
            CP16(sb +         phys, Ah + ga);
            CP16(sb + 16384 + phys, Al + ga);
            CP16(sb + 32768 + phys, Bh + gb);
            CP16(sb + 49152 + phys, Bl + gb);
        }
        CP_COMMIT();
    };

    load_stage(0, 0);

    int ahalf = lane >> 4;
    int bhalf = (lane >> 3) & 1;
    int arow = wm*64 + (lane & 15);
    int brow = wn*32 + ((lane >> 4) << 3) + (lane & 7);

    for (int kt = 0; kt < NKT; kt++) {
        if (kt + 1 < NKT) { load_stage(kt + 1, (kt + 1) & 1); CP_WAIT(1); }
        else              { CP_WAIT(0); }
        __syncthreads();

        uint32_t sb = sbase + (uint32_t)(kt & 1) * GSTG;
#pragma unroll
        for (int kk = 0; kk < 4; kk++) {
            uint32_t aswz = (uint32_t)(((2*kk + ahalf) ^ (arow & 7)) << 4);
            uint32_t bswz = (uint32_t)(((2*kk + bhalf) ^ (brow & 7)) << 4);
            uint32_t ah4[4][4], al4[4][4], bh4[2][4], bl4[2][4];
#pragma unroll
            for (int mf = 0; mf < 4; mf++) {
                uint32_t off = (uint32_t)((arow + mf*16) * 128) + aswz;
                ldm4(ah4[mf], sb + off);
                ldm4(al4[mf], sb + 16384 + off);
            }
#pragma unroll
            for (int nh = 0; nh < 2; nh++) {
                uint32_t off = (uint32_t)((brow + nh*16) * 128) + bswz;
                ldm4(bh4[nh], sb + 32768 + off);
                ldm4(bl4[nh], sb + 49152 + off);
            }
#pragma unroll
            for (int mf = 0; mf < 4; mf++)
#pragma unroll
                for (int nf = 0; nf < 4; nf++) {
                    const uint32_t* ph = bh4[nf >> 1] + (nf & 1)*2;
                    const uint32_t* pl = bl4[nf >> 1] + (nf & 1)*2;
                    mma_f32(acc[mf][nf], ah4[mf], ph);
                    mma_f32(acc[mf][nf], ah4[mf], pl);
                    mma_f32(acc[mf][nf], al4[mf], ph);
                }
        }
        __syncthreads();
    }

    int g = lane >> 2, t2 = (lane & 3) * 2;
#pragma unroll
    for (int nf = 0; nf < 4; nf++) {
        int col = n0 + wn*32 + nf*8 + t2;
        int lc = col & (CC - 1);
        float2 bb = *(const float2*)(bias + lc);
#pragma unroll
        for (int mf = 0; mf < 4; mf++) {
            int m1 = m0 + wm*64 + mf*16 + g;
            float v0 = acc[mf][nf][0] + bb.x, v1 = acc[mf][nf][1] + bb.y;
            float v2 = acc[mf][nf][2] + bb.x, v3 = acc[mf][nf][3] + bb.y;
            if (MODE == 0) {
                int h = lc >> 6, d = lc & 63;
                int b1 = m1 >> 11, t1 = m1 & (TT - 1);
                size_t base = ((size_t)(b1*HH + h)*TT) * DD + d;
                split_st(oh, ol, base + (size_t)t1*DD,       v0*scale, v1*scale);
                split_st(oh, ol, base + (size_t)(t1 + 8)*DD, v2*scale, v3*scale);
            } else {
                *(float2*)(outF + (size_t)m1*CC + col)       = make_float2(v0, v1);
                *(float2*)(outF + (size_t)(m1 + 8)*CC + col) = make_float2(v2, v3);
            }
        }
    }
}

// ---------------------------------------------------------------------------
// Tensor-core causal flash attention, fp16x3, f32 accumulate.
// OCC-2 version: __launch_bounds__(256, 2); Q fragments reloaded from smem
// per kk (frees 32 regs so two CTAs fit the register file).
// Block: 128 q-rows, 8 warps. k-tiles of 64, cp.async 2-stage. 96KB smem.
// ---------------------------------------------------------------------------
__global__ __launch_bounds__(256, 2) void attn_mma()
{
    extern __shared__ char smraw[];
    const uint32_t sb = smem_u32(smraw);
    const uint32_t QH = 0, QL = 16384, ST = 32768, STSZ = 32768;

    int tid = threadIdx.x, lane = tid & 31, w = tid >> 5;
    int bh = blockIdx.y;
    int qt = (int)gridDim.x - 1 - (int)blockIdx.x;
    int q0 = qt * 128;
    int nkt = 2*qt + 2;

    const h16* Qh = g_qh + (size_t)bh*TT*DD;
    const h16* Ql = g_ql + (size_t)bh*TT*DD;
    const h16* Kh = g_kh + (size_t)bh*TT*DD;
    const h16* Kl = g_kl + (size_t)bh*TT*DD;
    const h16* Vh = g_vh + (size_t)bh*TT*DD;
    const h16* Vl = g_vl + (size_t)bh*TT*DD;

    auto load_kv = [&](int kt, int s) {
        uint32_t base = sb + ST + (uint32_t)s * STSZ;
        int k0 = kt * 64;
#pragma unroll
        for (int i = 0; i < 2; i++) {
            int id = tid + i*256;
            int r = id >> 3, c = id & 7;
            uint32_t phys = (uint32_t)(r*128 + ((c ^ (r & 7)) << 4));
            size_t gsrc = (size_t)(k0 + r)*DD + c*8;
            CP16(base +         phys, Kh + gsrc);
            CP16(base +  8192 + phys, Kl + gsrc);
            CP16(base + 16384 + phys, Vh + gsrc);
            CP16(base + 24576 + phys, Vl + gsrc);
        }
        CP_COMMIT();
    };

#pragma unroll
    for (int m = 0; m < 2; m++)
#pragma unroll
        for (int i = 0; i < 4; i++) {
            int id = tid + i*256;
            int r = id >> 3, c = id & 7;
            uint32_t dst = sb + (m ? QL : QH) + (uint32_t)(r*128 + ((c ^ (r & 7)) << 4));
            const h16* src = (m ? Ql : Qh) + (size_t)(q0 + r)*DD + c*8;
            CP16(dst, src);
        }
    CP_COMMIT();
    load_kv(0, 0);

    CP_WAIT(1);
    __syncthreads();

    float oacc[8][4] = {};
    float mrow0 = -1e30f, mrow1 = -1e30f;
    float lsum0 = 0.f, lsum1 = 0.f;

    int g = lane >> 2, t2 = (lane & 3) * 2;
    int arow = w*16 + (lane & 15), ahalf = lane >> 4;
    int r0g = q0 + 16*w + g, r1g = r0g + 8;
    int bhalf = (lane >> 3) & 1;
    int vi = lane >> 3, vr = lane & 7;

    for (int kt = 0; kt < nkt; kt++) {
        if (kt + 1 < nkt) { load_kv(kt + 1, (kt + 1) & 1); CP_WAIT(1); }
        else              { CP_WAIT(0); }
        __syncthreads();

        int k0 = kt * 64;
        if (k0 <= q0 + 16*w + 15) {
            uint32_t st = sb + ST + (uint32_t)(kt & 1) * STSZ;

            // ---- S = Q K^T (Q frags reloaded from smem per kk) ----
            float sacc[8][4] = {};
#pragma unroll
            for (int kk = 0; kk < 4; kk++) {
                uint32_t qoff = (uint32_t)(arow*128 + (((2*kk + ahalf) ^ (arow & 7)) << 4));
                uint32_t qh4[4], ql4[4];
                ldm4(qh4, sb + QH + qoff);
                ldm4(ql4, sb + QL + qoff);
#pragma unroll
                for (int ng = 0; ng < 4; ng++) {
                    int brow = ng*16 + ((lane >> 4) << 3) + (lane & 7);
                    uint32_t off = (uint32_t)(brow*128 + (((2*kk + bhalf) ^ (brow & 7)) << 4));
                    uint32_t kh4[4], kl4[4];
                    ldm4(kh4, st + off);
                    ldm4(kl4, st + 8192 + off);
                    mma_f32(sacc[2*ng],   qh4, kh4);
                    mma_f32(sacc[2*ng],   qh4, kl4);
                    mma_f32(sacc[2*ng],   ql4, kh4);
                    mma_f32(sacc[2*ng+1], qh4, kh4 + 2);
                    mma_f32(sacc[2*ng+1], qh4, kl4 + 2);
                    mma_f32(sacc[2*ng+1], ql4, kh4 + 2);
                }
            }

            if (k0 + 63 > r0g) {
#pragma unroll
                for (int j = 0; j < 8; j++) {
                    int col = k0 + 8*j + t2;
                    if (col     > r0g) sacc[j][0] = -1e30f;
                    if (col + 1 > r0g) sacc[j][1] = -1e30f;
                    if (col     > r1g) sacc[j][2] = -1e30f;
                    if (col + 1 > r1g) sacc[j][3] = -1e30f;
                }
            }

            float tm0 = -1e30f, tm1 = -1e30f;
#pragma unroll
            for (int j = 0; j < 8; j++) {
                tm0 = fmaxf(tm0, fmaxf(sacc[j][0], sacc[j][1]));
                tm1 = fmaxf(tm1, fmaxf(sacc[j][2], sacc[j][3]));
            }
            tm0 = fmaxf(tm0, __shfl_xor_sync(0xffffffffu, tm0, 1));
            tm0 = fmaxf(tm0, __shfl_xor_sync(0xffffffffu, tm0, 2));
            tm1 = fmaxf(tm1, __shfl_xor_sync(0xffffffffu, tm1, 1));
            tm1 = fmaxf(tm1, __shfl_xor_sync(0xffffffffu, tm1, 2));
            float mn0 = fmaxf(mrow0, tm0), mn1 = fmaxf(mrow1, tm1);
            float c0 = __expf(mrow0 - mn0), c1 = __expf(mrow1 - mn1);
            mrow0 = mn0; mrow1 = mn1;

            float ps0 = 0.f, ps1 = 0.f;
            uint32_t pfh[4][4], pfl[4][4];
#pragma unroll
            for (int kc = 0; kc < 4; kc++) {
#pragma unroll
                for (int jj = 0; jj < 2; jj++) {
                    int j = 2*kc + jj;
                    float p0 = __expf(sacc[j][0] - mn0);
                    float p1 = __expf(sacc[j][1] - mn0);
                    float p2 = __expf(sacc[j][2] - mn1);
                    float p3 = __expf(sacc[j][3] - mn1);
                    ps0 += p0 + p1; ps1 += p2 + p3;
                    uint32_t hp01 = pk2h(p0, p1);
                    uint32_t hp23 = pk2h(p2, p3);
                    float2 b01 = h2f(hp01), b23 = h2f(hp23);
                    pfh[kc][2*jj]   = hp01;
                    pfh[kc][2*jj+1] = hp23;
                    pfl[kc][2*jj]   = pk2h(p0 - b01.x, p1 - b01.y);
                    pfl[kc][2*jj+1] = pk2h(p2 - b23.x, p3 - b23.y);
                }
            }
            lsum0 = lsum0 * c0 + ps0;
            lsum1 = lsum1 * c1 + ps1;
#pragma unroll
            for (int j = 0; j < 8; j++) {
                oacc[j][0] *= c0; oacc[j][1] *= c0;
                oacc[j][2] *= c1; oacc[j][3] *= c1;
            }

#pragma unroll
            for (int kc = 0; kc < 4; kc++) {
#pragma unroll
                for (int dg = 0; dg < 4; dg++) {
                    int key = kc*16 + 8*(vi & 1) + vr;
                    int dc = 2*dg + (vi >> 1);
                    uint32_t off = (uint32_t)(key*128 + ((dc ^ (key & 7)) << 4));
                    uint32_t vh4[4], vl4[4];
                    ldm4t(vh4, st + 16384 + off);
                    ldm4t(vl4, st + 24576 + off);
                    mma_f32(oacc[2*dg],   pfh[kc], vh4);
                    mma_f32(oacc[2*dg],   pfh[kc], vl4);
                    mma_f32(oacc[2*dg],   pfl[kc], vh4);
                    mma_f32(oacc[2*dg+1], pfh[kc], vh4 + 2);
                    mma_f32(oacc[2*dg+1], pfh[kc], vl4 + 2);
                    mma_f32(oacc[2*dg+1], pfl[kc], vh4 + 2);
                }
            }
        }
        __syncthreads();
    }

    lsum0 += __shfl_xor_sync(0xffffffffu, lsum0, 1);
    lsum0 += __shfl_xor_sync(0xffffffffu, lsum0, 2);
    lsum1 += __shfl_xor_sync(0xffffffffu, lsum1, 1);
    lsum1 += __shfl_xor_sync(0xffffffffu, lsum1, 2);
    float inv0 = 1.f / lsum0, inv1 = 1.f / lsum1;

    int b = bh >> 4, h = bh & 15;
    size_t row0 = (size_t)(b*TT + r0g) * CC + h*DD;
    size_t row1 = (size_t)(b*TT + r1g) * CC + h*DD;
#pragma unroll
    for (int j = 0; j < 8; j++) {
        int d = 8*j + t2;
        split_st(g_ah, g_al, row0 + d, oacc[j][0]*inv0, oacc[j][1]*inv0);
        split_st(g_ah, g_al, row1 + d, oacc[j][2]*inv1, oacc[j][3]*inv1);
    }
}

// ---------------------------------------------------------------------------
extern "C" void kernel_launch(void* const* d_in, const int* in_sizes, int n_in,
                              void* d_out, int out_size)
{
    (void)in_sizes; (void)n_in; (void)out_size;
    const float* x  = (const float*)d_in[0];
    const float* Wq = (const float*)d_in[1];
    const float* bq = (const float*)d_in[2];
    const float* Wk = (const float*)d_in[3];
    const float* bk = (const float*)d_in[4];
    const float* Wv = (const float*)d_in[5];
    const float* bv = (const float*)d_in[6];
    const float* Wo = (const float*)d_in[7];
    const float* bo = (const float*)d_in[8];
    float* out = (float*)d_out;

    h16 *xh, *xl, *ah, *al, *wh, *wl, *qh, *ql, *kh, *kl, *vh, *vl;
    cudaGetSymbolAddress((void**)&xh, g_xh);
    cudaGetSymbolAddress((void**)&xl, g_xl);
    cudaGetSymbolAddress((void**)&ah, g_ah);
    cudaGetSymbolAddress((void**)&al, g_al);
    cudaGetSymbolAddress((void**)&wh, g_wh);
    cudaGetSymbolAddress((void**)&wl, g_wl);
    cudaGetSymbolAddress((void**)&qh, g_qh);
    cudaGetSymbolAddress((void**)&ql, g_ql);
    cudaGetSymbolAddress((void**)&kh, g_kh);
    cudaGetSymbolAddress((void**)&kl, g_kl);
    cudaGetSymbolAddress((void**)&vh, g_vh);
    cudaGetSymbolAddress((void**)&vl, g_vl);

    // 1. split x
    split_kernel<<<(MM*CC/4)/256, 256>>>(x, xh, xl);

    // 2. transpose+split all 4 weights (one launch)
    tsplit_kernel<<<dim3(CC/32, CC/32, 4), dim3(32, 8)>>>(Wq, Wk, Wv, Wo, wh, wl);

    // 3. fused QKV projection (N=3072) -> split fp16 [B,H,T,D] (Q scaled 1/8)
    const int gsm = 2 * GSTG;  // 128 KB
    cudaFuncSetAttribute(gemm_f16x3<0>, cudaFuncAttributeMaxDynamicSharedMemorySize, gsm);
    cudaFuncSetAttribute(gemm_f16x3<1>, cudaFuncAttributeMaxDynamicSharedMemorySize, gsm);
    gemm_f16x3<0><<<dim3(3*CC/128, MM/128), 256, gsm>>>(
        xh, xl, wh, wl, bq, bk, bv,
        nullptr, qh, ql, kh, kl, vh, vl);

    // 4. tensor-core flash attention (occ-2)
    const int asm_sz = 98304;
    cudaFuncSetAttribute(attn_mma, cudaFuncAttributeMaxDynamicSharedMemorySize, asm_sz);
    attn_mma<<<dim3(TT/128, BB*HH), 256, asm_sz>>>();

    // 5. output projection -> d_out (fp32)
    gemm_f16x3<1><<<dim3(CC/128, MM/128), 256, gsm>>>(
        ah, al, wh + (size_t)3*CC*CC, wl + (size_t)3*CC*CC, bo, nullptr, nullptr,
        out, nullptr, nullptr, nullptr, nullptr, nullptr, nullptr);
}

// round 11
// speedup vs baseline: 1.0474x; 1.0146x over previous
#include <cuda_runtime.h>
#include <cuda_fp16.h>
#include <cstdint>

// B=2, T=2048, C=1024, H=16, D=64, causal MHA, fp32 in/out.
#define BB 2
#define TT 2048
#define CC 1024
#define HH 16
#define DD 64
#define MM (BB*TT)

typedef __half h16;

// ---------------- scratch (allocation-free) ----------------
__device__ h16 g_xh[MM*CC], g_xl[MM*CC];
__device__ h16 g_ah[MM*CC], g_al[MM*CC];
__device__ h16 g_wh[4*CC*CC], g_wl[4*CC*CC];   // [Wq|Wk|Wv|Wo] transposed [n][k]
__device__ h16 g_qh[BB*HH*TT*DD], g_ql[BB*HH*TT*DD];
__device__ h16 g_kh[BB*HH*TT*DD], g_kl[BB*HH*TT*DD];
__device__ h16 g_vh[BB*HH*TT*DD], g_vl[BB*HH*TT*DD];

// ---------------- helpers (sm_80-baseline PTX only) ----------------
__device__ __forceinline__ uint32_t smem_u32(const void* p) {
    return (uint32_t)__cvta_generic_to_shared(p);
}

#define CP16(dst, src) \
    asm volatile("cp.async.cg.shared.global [%0], [%1], 16;" :: "r"(dst), "l"(src) : "memory")
#define CP_COMMIT() asm volatile("cp.async.commit_group;" ::: "memory")
#define CP_WAIT(n)  asm volatile("cp.async.wait_group %0;" :: "n"(n) : "memory")

__device__ __forceinline__ void ldm4(uint32_t* r, uint32_t a) {
    asm volatile("ldmatrix.sync.aligned.m8n8.x4.shared.b16 {%0,%1,%2,%3}, [%4];"
                 : "=r"(r[0]), "=r"(r[1]), "=r"(r[2]), "=r"(r[3]) : "r"(a));
}
__device__ __forceinline__ void ldm4t(uint32_t* r, uint32_t a) {
    asm volatile("ldmatrix.sync.aligned.m8n8.x4.trans.shared.b16 {%0,%1,%2,%3}, [%4];"
                 : "=r"(r[0]), "=r"(r[1]), "=r"(r[2]), "=r"(r[3]) : "r"(a));
}
__device__ __forceinline__ void mma_f32(float* d, const uint32_t* a, const uint32_t* b) {
    asm volatile("mma.sync.aligned.m16n8k16.row.col.f32.f16.f16.f32 "
                 "{%0,%1,%2,%3}, {%4,%5,%6,%7}, {%8,%9}, {%0,%1,%2,%3};"
                 : "+f"(d[0]), "+f"(d[1]), "+f"(d[2]), "+f"(d[3])
                 : "r"(a[0]), "r"(a[1]), "r"(a[2]), "r"(a[3]), "r"(b[0]), "r"(b[1]));
}

__device__ __forceinline__ float2 h2f(uint32_t u) {
    __half2 h = *reinterpret_cast<__half2*>(&u);
    return __half22float2(h);
}
__device__ __forceinline__ uint32_t pk2h(float a, float b) {
    __half2 t = __floats2half2_rn(a, b);
    return *reinterpret_cast<uint32_t*>(&t);
}
__device__ __forceinline__ void split_st(h16* hi, h16* lo, size_t off, float a, float b) {
    uint32_t hp = pk2h(a, b);
    float2 back = h2f(hp);
    *(uint32_t*)(hi + off) = hp;
    *(uint32_t*)(lo + off) = pk2h(a - back.x, b - back.y);
}

// ---------------------------------------------------------------------------
__global__ void split_kernel(const float* __restrict__ x,
                             h16* __restrict__ hi, h16* __restrict__ lo) {
    int i = blockIdx.x * blockDim.x + threadIdx.x;
    float4 v = ((const float4*)x)[i];
    split_st(hi, lo, 4*(size_t)i,     v.x, v.y);
    split_st(hi, lo, 4*(size_t)i + 2, v.z, v.w);
}

// ---------------------------------------------------------------------------
__global__ void tsplit_kernel(const float* __restrict__ W0, const float* __restrict__ W1,
                              const float* __restrict__ W2, const float* __restrict__ W3,
                              h16* __restrict__ hi, h16* __restrict__ lo) {
    __shared__ float t[32][33];
    int tx = threadIdx.x, ty = threadIdx.y;          // (32, 8)
    int n0 = blockIdx.x * 32, k0 = blockIdx.y * 32;
    int z = blockIdx.z;
    const float* W = (z == 0) ? W0 : (z == 1) ? W1 : (z == 2) ? W2 : W3;
    h16* hz = hi + (size_t)z * CC * CC;
    h16* lz = lo + (size_t)z * CC * CC;
#pragma unroll
    for (int i = 0; i < 4; i++)
        t[ty + 8*i][tx] = W[(size_t)(k0 + ty + 8*i) * CC + n0 + tx];
    __syncthreads();
#pragma unroll
    for (int i = 0; i < 4; i++) {
        float v = t[tx][ty + 8*i];
        __half h = __float2half_rn(v);
        size_t o = (size_t)(n0 + ty + 8*i) * CC + k0 + tx;
        hz[o] = h;
        lz[o] = __float2half_rn(v - __half2float(h));
    }
}

// ---------------------------------------------------------------------------
// fp16x3 GEMM (uniform f32-acc): 128x128 tile, K-chunk 64, 2-stage cp.async.
// MODE 0: fused QKV (grid.x covers N=3072), split-fp16 out to [B,H,T,D].
// MODE 1: single GEMM (Wo), fp32 [M,N].
// ---------------------------------------------------------------------------
#define GSTG 65536
#define NKT  16

template<int MODE>
__global__ __launch_bounds__(256) void gemm_f16x3(
    const h16* __restrict__ Ah, const h16* __restrict__ Al,
    const h16* __restrict__ Bh, const h16* __restrict__ Bl,
    const float* __restrict__ bias0, const float* __restrict__ bias1,
    const float* __restrict__ bias2,
    float* __restrict__ outF,
    h16* __restrict__ o0h, h16* __restrict__ o0l,
    h16* __restrict__ o1h, h16* __restrict__ o1l,
    h16* __restrict__ o2h, h16* __restrict__ o2l)
{
    extern __shared__ char smraw[];
    const uint32_t sbase = smem_u32(smraw);

    int tid = threadIdx.x, lane = tid & 31, wid = tid >> 5;
    int wm = wid & 1, wn = wid >> 1;
    int m0 = blockIdx.y << 7, n0 = blockIdx.x << 7;

    const float* bias = bias0;
    h16 *oh = o0h, *ol = o0l;
    float scale = 1.0f;
    if (MODE == 0) {
        int sec = n0 >> 10;
        bias = (sec == 0) ? bias0 : (sec == 1) ? bias1 : bias2;
        oh   = (sec == 0) ? o0h   : (sec == 1) ? o1h   : o2h;
        ol   = (sec == 0) ? o0l   : (sec == 1) ? o1l   : o2l;
        scale = (sec == 0) ? 0.125f : 1.0f;
    }

    float acc[4][4][4] = {};

    auto load_stage = [&](int kt, int s) {
        uint32_t sb = sbase + (uint32_t)s * GSTG;
#pragma unroll
        for (int i = 0; i < 4; i++) {
            int id = tid + i*256;
            int r = id >> 3, c = id & 7;
            uint32_t phys = (uint32_t)(r*128 + ((c ^ (r & 7)) << 4));
            size_t ga = (size_t)(m0 + r)*CC + kt*64 + c*8;
            size_t gb = (size_t)(n0 + r)*CC + kt*64 + c*8;
            CP16(sb +         phys, Ah + ga);
            CP16(sb + 16384 + phys, Al + ga);
            CP16(sb + 32768 + phys, Bh + gb);
            CP16(sb + 49152 + phys, Bl + gb);
        }
        CP_COMMIT();
    };

    load_stage(0, 0);

    int ahalf = lane >> 4;
    int bhalf = (lane >> 3) & 1;
    int arow = wm*64 + (lane & 15);
    int brow = wn*32 + ((lane >> 4) << 3) + (lane & 7);

    for (int kt = 0; kt < NKT; kt++) {
        if (kt + 1 < NKT) { load_stage(kt + 1, (kt + 1) & 1); CP_WAIT(1); }
        else              { CP_WAIT(0); }
        __syncthreads();

        uint32_t sb = sbase + (uint32_t)(kt & 1) * GSTG;
#pragma unroll
        for (int kk = 0; kk < 4; kk++) {
            uint32_t aswz = (uint32_t)(((2*kk + ahalf) ^ (arow & 7)) << 4);
            uint32_t bswz = (uint32_t)(((2*kk + bhalf) ^ (brow & 7)) << 4);
            uint32_t ah4[4][4], al4[4][4], bh4[2][4], bl4[2][4];
#pragma unroll
            for (int mf = 0; mf < 4; mf++) {
                uint32_t off = (uint32_t)((arow + mf*16) * 128) + aswz;
                ldm4(ah4[mf], sb + off);
                ldm4(al4[mf], sb + 16384 + off);
            }
#pragma unroll
            for (int nh = 0; nh < 2; nh++) {
                uint32_t off = (uint32_t)((brow + nh*16) * 128) + bswz;
                ldm4(bh4[nh], sb + 32768 + off);
                ldm4(bl4[nh], sb + 49152 + off);
            }
#pragma unroll
            for (int mf = 0; mf < 4; mf++)
#pragma unroll
                for (int nf = 0; nf < 4; nf++) {
                    const uint32_t* ph = bh4[nf >> 1] + (nf & 1)*2;
                    const uint32_t* pl = bl4[nf >> 1] + (nf & 1)*2;
                    mma_f32(acc[mf][nf], ah4[mf], ph);
                    mma_f32(acc[mf][nf], ah4[mf], pl);
                    mma_f32(acc[mf][nf], al4[mf], ph);
                }
        }
        __syncthreads();
    }

    int g = lane >> 2, t2 = (lane & 3) * 2;
#pragma unroll
    for (int nf = 0; nf < 4; nf++) {
        int col = n0 + wn*32 + nf*8 + t2;
        int lc = col & (CC - 1);
        float2 bb = *(const float2*)(bias + lc);
#pragma unroll
        for (int mf = 0; mf < 4; mf++) {
            int m1 = m0 + wm*64 + mf*16 + g;
            float v0 = acc[mf][nf][0] + bb.x, v1 = acc[mf][nf][1] + bb.y;
            float v2 = acc[mf][nf][2] + bb.x, v3 = acc[mf][nf][3] + bb.y;
            if (MODE == 0) {
                int h = lc >> 6, d = lc & 63;
                int b1 = m1 >> 11, t1 = m1 & (TT - 1);
                size_t base = ((size_t)(b1*HH + h)*TT) * DD + d;
                split_st(oh, ol, base + (size_t)t1*DD,       v0*scale, v1*scale);
                split_st(oh, ol, base + (size_t)(t1 + 8)*DD, v2*scale, v3*scale);
            } else {
                *(float2*)(outF + (size_t)m1*CC + col)       = make_float2(v0, v1);
                *(float2*)(outF + (size_t)(m1 + 8)*CC + col) = make_float2(v2, v3);
            }
        }
    }
}

// ---------------------------------------------------------------------------
// Tensor-core causal flash attention, fp16x3, f32 accumulate.
// K-TILE 128 version: q-tile 128, k-tile 128, Q frags resident, occ-1.
// smem: Qh(16K) Ql(16K) | 2 stages x [Kh Kl Vh Vl](16K each) = 160KB.
// Halved per-tile fixed costs (barriers, rescales, shuffles) vs k-tile 64.
// ---------------------------------------------------------------------------
__global__ __launch_bounds__(256) void attn_mma()
{
    extern __shared__ char smraw[];
    const uint32_t sb = smem_u32(smraw);
    const uint32_t QH = 0, QL = 16384, ST = 32768, STSZ = 65536;

    int tid = threadIdx.x, lane = tid & 31, w = tid >> 5;
    int bh = blockIdx.y;
    int qt = (int)gridDim.x - 1 - (int)blockIdx.x;   // heavy tiles first
    int q0 = qt * 128;
    int nkt = qt + 1;

    const h16* Qh = g_qh + (size_t)bh*TT*DD;
    const h16* Ql = g_ql + (size_t)bh*TT*DD;
    const h16* Kh = g_kh + (size_t)bh*TT*DD;
    const h16* Kl = g_kl + (size_t)bh*TT*DD;
    const h16* Vh = g_vh + (size_t)bh*TT*DD;
    const h16* Vl = g_vl + (size_t)bh*TT*DD;

    // stage loader: 4 matrices x 128 rows x 8 16B-chunks = 16/thread
    auto load_kv = [&](int kt, int s) {
        uint32_t base = sb + ST + (uint32_t)s * STSZ;
        int k0 = kt * 128;
#pragma unroll
        for (int i = 0; i < 4; i++) {
            int id = tid + i*256;
            int r = id >> 3, c = id & 7;
            uint32_t phys = (uint32_t)(r*128 + ((c ^ (r & 7)) << 4));
            size_t gsrc = (size_t)(k0 + r)*DD + c*8;
            CP16(base +         phys, Kh + gsrc);
            CP16(base + 16384 + phys, Kl + gsrc);
            CP16(base + 32768 + phys, Vh + gsrc);
            CP16(base + 49152 + phys, Vl + gsrc);
        }
        CP_COMMIT();
    };

    // Q tile (128 x 64) hi/lo
#pragma unroll
    for (int m = 0; m < 2; m++)
#pragma unroll
        for (int i = 0; i < 4; i++) {
            int id = tid + i*256;
            int r = id >> 3, c = id & 7;
            uint32_t dst = sb + (m ? QL : QH) + (uint32_t)(r*128 + ((c ^ (r & 7)) << 4));
            const h16* src = (m ? Ql : Qh) + (size_t)(q0 + r)*DD + c*8;
            CP16(dst, src);
        }
    CP_COMMIT();
    load_kv(0, 0);

    CP_WAIT(1);               // Q ready (kv0 may still be in flight)
    __syncthreads();

    // Q fragments (resident for whole kernel)
    uint32_t qfh[4][4], qfl[4][4];
    int arow = w*16 + (lane & 15), ahalf = lane >> 4;
#pragma unroll
    for (int kk = 0; kk < 4; kk++) {
        uint32_t off = (uint32_t)(arow*128 + (((2*kk + ahalf) ^ (arow & 7)) << 4));
        ldm4(qfh[kk], sb + QH + off);
        ldm4(qfl[kk], sb + QL + off);
    }

    float oacc[8][4] = {};
    float mrow0 = -1e30f, mrow1 = -1e30f;
    float lsum0 = 0.f, lsum1 = 0.f;

    int g = lane >> 2, t2 = (lane & 3) * 2;
    int r0g = q0 + 16*w + g, r1g = r0g + 8;
    int bhalf = (lane >> 3) & 1;
    int vi = lane >> 3, vr = lane & 7;

    for (int kt = 0; kt < nkt; kt++) {
        if (kt + 1 < nkt) { load_kv(kt + 1, (kt + 1) & 1); CP_WAIT(1); }
        else              { CP_WAIT(0); }
        __syncthreads();

        int k0 = kt * 128;
        if (k0 <= q0 + 16*w + 15) {   // skip fully-masked warps on diagonal tile
            uint32_t st = sb + ST + (uint32_t)(kt & 1) * STSZ;

            // ---- S = Q K^T over 128 keys (16 j-fragments) ----
            float sacc[16][4] = {};
#pragma unroll
            for (int kk = 0; kk < 4; kk++) {
#pragma unroll
                for (int ng = 0; ng < 8; ng++) {
                    int brow = ng*16 + ((lane >> 4) << 3) + (lane & 7);
                    uint32_t off = (uint32_t)(brow*128 + (((2*kk + bhalf) ^ (brow & 7)) << 4));
                    uint32_t kh4[4], kl4[4];
                    ldm4(kh4, st + off);
                    ldm4(kl4, st + 16384 + off);
                    mma_f32(sacc[2*ng],   qfh[kk], kh4);
                    mma_f32(sacc[2*ng],   qfh[kk], kl4);
                    mma_f32(sacc[2*ng],   qfl[kk], kh4);
                    mma_f32(sacc[2*ng+1], qfh[kk], kh4 + 2);
                    mma_f32(sacc[2*ng+1], qfh[kk], kl4 + 2);
                    mma_f32(sacc[2*ng+1], qfl[kk], kh4 + 2);
                }
            }

            // ---- causal mask ----
            if (k0 + 127 > r0g) {
#pragma unroll
                for (int j = 0; j < 16; j++) {
                    int col = k0 + 8*j + t2;
                    if (col     > r0g) sacc[j][0] = -1e30f;
                    if (col + 1 > r0g) sacc[j][1] = -1e30f;
                    if (col     > r1g) sacc[j][2] = -1e30f;
                    if (col + 1 > r1g) sacc[j][3] = -1e30f;
                }
            }

            // ---- online softmax ----
            float tm0 = -1e30f, tm1 = -1e30f;
#pragma unroll
            for (int j = 0; j < 16; j++) {
                tm0 = fmaxf(tm0, fmaxf(sacc[j][0], sacc[j][1]));
                tm1 = fmaxf(tm1, fmaxf(sacc[j][2], sacc[j][3]));
            }
            tm0 = fmaxf(tm0, __shfl_xor_sync(0xffffffffu, tm0, 1));
            tm0 = fmaxf(tm0, __shfl_xor_sync(0xffffffffu, tm0, 2));
            tm1 = fmaxf(tm1, __shfl_xor_sync(0xffffffffu, tm1, 1));
            tm1 = fmaxf(tm1, __shfl_xor_sync(0xffffffffu, tm1, 2));
            float mn0 = fmaxf(mrow0, tm0), mn1 = fmaxf(mrow1, tm1);
            float c0 = __expf(mrow0 - mn0), c1 = __expf(mrow1 - mn1);
            mrow0 = mn0; mrow1 = mn1;

            float ps0 = 0.f, ps1 = 0.f;
            uint32_t pfh[8][4], pfl[8][4];
#pragma unroll
            for (int kc = 0; kc < 8; kc++) {
#pragma unroll
                for (int jj = 0; jj < 2; jj++) {
                    int j = 2*kc + jj;
                    float p0 = __expf(sacc[j][0] - mn0);
                    float p1 = __expf(sacc[j][1] - mn0);
                    float p2 = __expf(sacc[j][2] - mn1);
                    float p3 = __expf(sacc[j][3] - mn1);
                    ps0 += p0 + p1; ps1 += p2 + p3;
                    uint32_t hp01 = pk2h(p0, p1);
                    uint32_t hp23 = pk2h(p2, p3);
                    float2 b01 = h2f(hp01), b23 = h2f(hp23);
                    pfh[kc][2*jj]   = hp01;
                    pfh[kc][2*jj+1] = hp23;
                    pfl[kc][2*jj]   = pk2h(p0 - b01.x, p1 - b01.y);
                    pfl[kc][2*jj+1] = pk2h(p2 - b23.x, p3 - b23.y);
                }
            }
            lsum0 = lsum0 * c0 + ps0;
            lsum1 = lsum1 * c1 + ps1;
#pragma unroll
            for (int j = 0; j < 8; j++) {
                oacc[j][0] *= c0; oacc[j][1] *= c0;
                oacc[j][2] *= c1; oacc[j][3] *= c1;
            }

            // ---- O += P V over 128 keys ----
#pragma unroll
            for (int kc = 0; kc < 8; kc++) {
#pragma unroll
                for (int dg = 0; dg < 4; dg++) {
                    int key = kc*16 + 8*(vi & 1) + vr;
                    int dc = 2*dg + (vi >> 1);
                    uint32_t off = (uint32_t)(key*128 + ((dc ^ (key & 7)) << 4));
                    uint32_t vh4[4], vl4[4];
                    ldm4t(vh4, st + 32768 + off);
                    ldm4t(vl4, st + 49152 + off);
                    mma_f32(oacc[2*dg],   pfh[kc], vh4);
                    mma_f32(oacc[2*dg],   pfh[kc], vl4);
                    mma_f32(oacc[2*dg],   pfl[kc], vh4);
                    mma_f32(oacc[2*dg+1], pfh[kc], vh4 + 2);
                    mma_f32(oacc[2*dg+1], pfh[kc], vl4 + 2);
                    mma_f32(oacc[2*dg+1], pfl[kc], vh4 + 2);
                }
            }
        }
        __syncthreads();
    }

    lsum0 += __shfl_xor_sync(0xffffffffu, lsum0, 1);
    lsum0 += __shfl_xor_sync(0xffffffffu, lsum0, 2);
    lsum1 += __shfl_xor_sync(0xffffffffu, lsum1, 1);
    lsum1 += __shfl_xor_sync(0xffffffffu, lsum1, 2);
    float inv0 = 1.f / lsum0, inv1 = 1.f / lsum1;

    int b = bh >> 4, h = bh & 15;
    size_t row0 = (size_t)(b*TT + r0g) * CC + h*DD;
    size_t row1 = (size_t)(b*TT + r1g) * CC + h*DD;
#pragma unroll
    for (int j = 0; j < 8; j++) {
        int d = 8*j + t2;
        split_st(g_ah, g_al, row0 + d, oacc[j][0]*inv0, oacc[j][1]*inv0);
        split_st(g_ah, g_al, row1 + d, oacc[j][2]*inv1, oacc[j][3]*inv1);
    }
}

// ---------------------------------------------------------------------------
extern "C" void kernel_launch(void* const* d_in, const int* in_sizes, int n_in,
                              void* d_out, int out_size)
{
    (void)in_sizes; (void)n_in; (void)out_size;
    const float* x  = (const float*)d_in[0];
    const float* Wq = (const float*)d_in[1];
    const float* bq = (const float*)d_in[2];
    const float* Wk = (const float*)d_in[3];
    const float* bk = (const float*)d_in[4];
    const float* Wv = (const float*)d_in[5];
    const float* bv = (const float*)d_in[6];
    const float* Wo = (const float*)d_in[7];
    const float* bo = (const float*)d_in[8];
    float* out = (float*)d_out;

    h16 *xh, *xl, *ah, *al, *wh, *wl, *qh, *ql, *kh, *kl, *vh, *vl;
    cudaGetSymbolAddress((void**)&xh, g_xh);
    cudaGetSymbolAddress((void**)&xl, g_xl);
    cudaGetSymbolAddress((void**)&ah, g_ah);
    cudaGetSymbolAddress((void**)&al, g_al);
    cudaGetSymbolAddress((void**)&wh, g_wh);
    cudaGetSymbolAddress((void**)&wl, g_wl);
    cudaGetSymbolAddress((void**)&qh, g_qh);
    cudaGetSymbolAddress((void**)&ql, g_ql);
    cudaGetSymbolAddress((void**)&kh, g_kh);
    cudaGetSymbolAddress((void**)&kl, g_kl);
    cudaGetSymbolAddress((void**)&vh, g_vh);
    cudaGetSymbolAddress((void**)&vl, g_vl);

    // 1. split x
    split_kernel<<<(MM*CC/4)/256, 256>>>(x, xh, xl);

    // 2. transpose+split all 4 weights (one launch)
    tsplit_kernel<<<dim3(CC/32, CC/32, 4), dim3(32, 8)>>>(Wq, Wk, Wv, Wo, wh, wl);

    // 3. fused QKV projection (N=3072) -> split fp16 [B,H,T,D] (Q scaled 1/8)
    const int gsm = 2 * GSTG;  // 128 KB
    cudaFuncSetAttribute(gemm_f16x3<0>, cudaFuncAttributeMaxDynamicSharedMemorySize, gsm);
    cudaFuncSetAttribute(gemm_f16x3<1>, cudaFuncAttributeMaxDynamicSharedMemorySize, gsm);
    gemm_f16x3<0><<<dim3(3*CC/128, MM/128), 256, gsm>>>(
        xh, xl, wh, wl, bq, bk, bv,
        nullptr, qh, ql, kh, kl, vh, vl);

    // 4. tensor-core flash attention (k-tile 128)
    const int asm_sz = 32768 + 2*65536;   // 163840
    cudaFuncSetAttribute(attn_mma, cudaFuncAttributeMaxDynamicSharedMemorySize, asm_sz);
    attn_mma<<<dim3(TT/128, BB*HH), 256, asm_sz>>>();

    // 5. output projection -> d_out (fp32)
    gemm_f16x3<1><<<dim3(CC/128, MM/128), 256, gsm>>>(
        ah, al, wh + (size_t)3*CC*CC, wl + (size_t)3*CC*CC, bo, nullptr, nullptr,
        out, nullptr, nullptr, nullptr, nullptr, nullptr, nullptr);
}